// round 4
// baseline (speedup 1.0000x reference)
#include <cuda_runtime.h>
#include <cuda.h>
#include <cuda_fp16.h>
#include <cstdint>

#define B     16
#define CIN   512
#define COUT  512
#define WDIM  512
#define RES   64
#define LRELU 0.2f
#define GAINV 1.4142135623730951f
#define PADW  66
#define NPIX  (PADW * PADW)   // 4356

// int8 quantization scales (per-tensor, compile-time)
#define INV_SXH 3.96875f        // 127/32      (x_hi range +-32)
#define INV_SXL 16256.0f        // 127/0.0078125 (x_lo = half-ulp at |x|<32)
#define INV_SWH 21.166666f      // 127/6       (w range +-6)
#define INV_SWL 65024.0f        // 127/0.001953125
#define CA_SCALE (0.0625f   / 16129.0f)   // SWL*SXH = (0.001953125*32)/127^2
#define CB_SCALE (0.046875f / 16129.0f)   // SWH*SXL = (6*0.0078125)/127^2

// ---------------- scratch (device globals; no allocation allowed) ----------
__device__ float g_styles[B * CIN];
__device__ float g_wsq[COUT * CIN];
__device__ float g_dcoef[B * COUT];
__device__ __align__(1024) __half  g_xs_hi[(size_t)B * NPIX * CIN];
__device__ __align__(1024) __half  g_w_hi [(size_t)9 * COUT * CIN];
__device__ __align__(1024) int8_t  g_xq_hi[(size_t)B * NPIX * CIN];
__device__ __align__(1024) int8_t  g_xq_lo[(size_t)B * NPIX * CIN];
__device__ __align__(1024) int8_t  g_wq_hi[(size_t)9 * COUT * CIN];
__device__ __align__(1024) int8_t  g_wq_lo[(size_t)9 * COUT * CIN];

// ---------------- PTX helpers ----------------------------------------------
__device__ __forceinline__ uint32_t smem_to_u32(const void* p) {
    uint32_t a;
    asm("{ .reg .u64 t; cvta.to.shared.u64 t, %1; cvt.u32.u64 %0, t; }"
        : "=r"(a) : "l"(p));
    return a;
}

#define MBARRIER_INIT(mbar, count) \
    asm volatile("mbarrier.init.shared.b64 [%0], %1;" \
        :: "r"((uint32_t)(mbar)), "r"((uint32_t)(count)) : "memory")
#define MBARRIER_EXPECT_TX(mbar, tx) \
    asm volatile("mbarrier.arrive.expect_tx.shared.b64 _, [%0], %1;" \
        :: "r"((uint32_t)(mbar)), "r"((uint32_t)(tx)) : "memory")
#define MBARRIER_ARRIVE(mbar) \
    asm volatile("mbarrier.arrive.shared.b64 _, [%0];" \
        :: "r"((uint32_t)(mbar)) : "memory")

#define MBARRIER_WAIT_PARITY(mbar, par) do { \
    uint32_t _m = (uint32_t)(mbar); uint32_t _p = (uint32_t)(par); uint32_t _d; \
    asm volatile("{\n\t.reg .pred p;\n\t" \
        "mbarrier.try_wait.parity.acquire.cta.shared::cta.b64 p, [%1], %2;\n\t" \
        "selp.b32 %0, 1, 0, p;\n\t}" : "=r"(_d) : "r"(_m), "r"(_p) : "memory"); \
    if (!_d) { \
        asm volatile("{\n\t.reg .pred P1;\n\tWL_%=:\n\t" \
            "mbarrier.try_wait.parity.acquire.cta.shared::cta.b64 P1, [%0], %1, 0x989680;\n\t" \
            "@P1 bra.uni WD_%=;\n\tbra.uni WL_%=;\n\tWD_%=:\n\t}" \
            :: "r"(_m), "r"(_p) : "memory"); \
    } } while (0)

#define MBARRIER_WAIT_PARITY_RELAXED(mbar, par) do { \
    uint32_t _m = (uint32_t)(mbar); uint32_t _p = (uint32_t)(par); uint32_t _d; \
    asm volatile("{\n\t.reg .pred p;\n\t" \
        "mbarrier.try_wait.parity.relaxed.cta.shared::cta.b64 p, [%1], %2, 0x989680;\n\t" \
        "selp.b32 %0, 1, 0, p;\n\t}" : "=r"(_d) : "r"(_m), "r"(_p) : "memory"); \
    if (!_d) { \
        asm volatile("{\n\t.reg .pred P1;\n\tWL_%=:\n\t" \
            "mbarrier.try_wait.parity.relaxed.cta.shared::cta.b64 P1, [%0], %1, 0x989680;\n\t" \
            "@P1 bra.uni WD_%=;\n\tbra.uni WL_%=;\n\tWD_%=:\n\t}" \
            :: "r"(_m), "r"(_p) : "memory"); \
    } } while (0)

#define TMA_LOAD_3D(smem_addr, tmap, cx, cy, cz, mbar) \
    asm volatile("cp.async.bulk.tensor.3d.shared::cta.global.tile.mbarrier::complete_tx::bytes " \
        "[%0], [%1, {%2, %3, %4}], [%5];" \
        :: "r"((uint32_t)(smem_addr)), "l"(tmap), "r"((int32_t)(cx)), \
           "r"((int32_t)(cy)), "r"((int32_t)(cz)), "r"((uint32_t)(mbar)) : "memory")

__device__ __forceinline__ void ldsm4(uint32_t* r, uint32_t addr) {
    asm volatile("ldmatrix.sync.aligned.m8n8.x4.shared.b16 {%0,%1,%2,%3}, [%4];"
        : "=r"(r[0]), "=r"(r[1]), "=r"(r[2]), "=r"(r[3]) : "r"(addr));
}
__device__ __forceinline__ void mma16816(float* c, const uint32_t* a,
                                         const uint32_t* b) {
    asm volatile("mma.sync.aligned.m16n8k16.row.col.f32.f16.f16.f32 "
        "{%0,%1,%2,%3}, {%4,%5,%6,%7}, {%8,%9}, {%0,%1,%2,%3};"
        : "+f"(c[0]), "+f"(c[1]), "+f"(c[2]), "+f"(c[3])
        : "r"(a[0]), "r"(a[1]), "r"(a[2]), "r"(a[3]), "r"(b[0]), "r"(b[1]));
}
__device__ __forceinline__ void mma_s8(int32_t* c, const uint32_t* a,
                                       const uint32_t* b) {
    asm volatile("mma.sync.aligned.m16n8k32.row.col.s32.s8.s8.s32 "
        "{%0,%1,%2,%3}, {%4,%5,%6,%7}, {%8,%9}, {%0,%1,%2,%3};"
        : "+r"(c[0]), "+r"(c[1]), "+r"(c[2]), "+r"(c[3])
        : "r"(a[0]), "r"(a[1]), "r"(a[2]), "r"(a[3]), "r"(b[0]), "r"(b[1]));
}

__device__ __forceinline__ int8_t q8(float v, float inv_s) {
    int q = __float2int_rn(v * inv_s);
    q = max(-127, min(127, q));
    return (int8_t)q;
}

// ---------------------------------------------------------------------------
// Prep kernels
// ---------------------------------------------------------------------------
__global__ void styles_kernel(const float* __restrict__ w,
                              const float* __restrict__ aw,
                              const float* __restrict__ ab) {
    int warp = (blockIdx.x * blockDim.x + threadIdx.x) >> 5;
    int lane = threadIdx.x & 31;
    if (warp >= B * CIN) return;
    int b = warp / CIN, c = warp % CIN;
    const float* wr = w + b * WDIM;
    const float* ar = aw + c * WDIM;
    float sum = 0.f;
    for (int d = lane; d < WDIM; d += 32) sum += wr[d] * ar[d];
    #pragma unroll
    for (int o = 16; o; o >>= 1) sum += __shfl_xor_sync(0xffffffffu, sum, o);
    if (lane == 0) g_styles[warp] = sum * 0.044194173824159216f + ab[c];
}

__global__ void wsq_kernel(const float* __restrict__ weight) {
    int i = blockIdx.x * blockDim.x + threadIdx.x;
    if (i >= COUT * CIN) return;
    const float* p = weight + (size_t)i * 9;
    float s = 0.f;
    #pragma unroll
    for (int k = 0; k < 9; k++) s += p[k] * p[k];
    g_wsq[i] = s;
}

__global__ void dcoef_kernel() {
    int warp = (blockIdx.x * blockDim.x + threadIdx.x) >> 5;
    int lane = threadIdx.x & 31;
    if (warp >= B * COUT) return;
    int b = warp / COUT, o = warp % COUT;
    const float* sr = g_styles + b * CIN;
    const float* wr = g_wsq + o * CIN;
    float sum = 0.f;
    for (int c = lane; c < CIN; c += 32) {
        float s = sr[c];
        sum += s * s * wr[c];
    }
    #pragma unroll
    for (int k = 16; k; k >>= 1) sum += __shfl_xor_sync(0xffffffffu, sum, k);
    if (lane == 0) g_dcoef[warp] = rsqrtf(sum + 1e-8f);
}

// weight [oc][cin][9] fp32 -> w_hi fp16, wq_hi/wq_lo int8 at [tap][oc][cin]
__global__ void wsplit_kernel(const float* __restrict__ wt) {
    int i = blockIdx.x * blockDim.x + threadIdx.x;
    if (i >= COUT * CIN * 9) return;
    int cin = i % CIN;
    int rest = i / CIN;
    int oc = rest % COUT;
    int tap = rest / COUT;
    float v = wt[((size_t)oc * CIN + cin) * 9 + tap];
    __half hv = __float2half_rn(v);
    float hf = __half2float(hv);
    float lf = v - hf;
    size_t o = ((size_t)tap * COUT + oc) * CIN + cin;
    g_w_hi[o]  = hv;
    g_wq_hi[o] = q8(hf, INV_SWH);
    g_wq_lo[o] = q8(lf, INV_SWL);
}

// zero the padded borders (rows never written by xsplit)
__global__ void xborder_kernel() {
    int r = blockIdx.x * blockDim.x + threadIdx.x;
    if (r >= B * NPIX) return;
    int pp = r % NPIX;
    int pr = pp / PADW, pc = pp % PADW;
    if (pr == 0 || pr == PADW - 1 || pc == 0 || pc == PADW - 1) {
        uint4 z = {0, 0, 0, 0};
        uint4* a = (uint4*)(g_xs_hi + (size_t)r * CIN);
        #pragma unroll 4
        for (int k = 0; k < CIN / 8; k++) a[k] = z;
        uint4* qh = (uint4*)(g_xq_hi + (size_t)r * CIN);
        uint4* ql = (uint4*)(g_xq_lo + (size_t)r * CIN);
        #pragma unroll 4
        for (int k = 0; k < CIN / 16; k++) { qh[k] = z; ql[k] = z; }
    }
}

// x [b][c][64][64] * style -> x_hi fp16 + xq_hi/xq_lo int8, [b][pix][c]
__global__ __launch_bounds__(256) void xsplit_kernel(const float* __restrict__ x) {
    __shared__ float s[64][65];
    int h = blockIdx.x, b = blockIdx.y;
    int tid = threadIdx.x;
    int rowbase = (h + 1) * PADW + 1;
    for (int c0 = 0; c0 < CIN; c0 += 64) {
        #pragma unroll
        for (int i = tid; i < 4096; i += 256) {
            int cc = i >> 6, w = i & 63;
            s[cc][w] = x[(((size_t)b * CIN + c0 + cc) * RES + h) * RES + w]
                       * g_styles[b * CIN + c0 + cc];
        }
        __syncthreads();
        #pragma unroll
        for (int i = tid; i < 4096; i += 256) {
            int w = i >> 6, cc = i & 63;
            float v = s[cc][w];
            __half hv = __float2half_rn(v);
            float hf = __half2float(hv);
            float lf = v - hf;
            size_t o = ((size_t)b * NPIX + rowbase + w) * CIN + c0 + cc;
            g_xs_hi[o]  = hv;
            g_xq_hi[o] = q8(hf, INV_SXH);
            g_xq_lo[o] = q8(lf, INV_SXL);
        }
        __syncthreads();
    }
}

// ---------------------------------------------------------------------------
// Main MMA conv kernel: 3 phases
//  A: wq_lo(s8) x xq_hi(s8)   4 kc-chunks of 128 cin
//  B: wq_hi(s8) x xq_lo(s8)   4 kc-chunks of 128 cin
//  C: w_hi(f16) x x_hi(f16)   8 kc-chunks of 64 cin
// All tiles are 128B rows -> identical smem layout / swizzle / ldmatrix maps.
// ---------------------------------------------------------------------------
#define A_STAGES 4
#define B_STAGES 2
#define A_BYTES  16384          // 128 rows x 128B
#define B_SEG    17408          // 136-row slot (132 used), 1024-aligned
#define B_BYTES  (2 * B_SEG)
#define B_TX     33792          // 264 rows x 128B

#define OFF_AF(s)  ((s) * 8)
#define OFF_AE(s)  (32 + (s) * 8)
#define OFF_BF(s)  (64 + (s) * 8)
#define OFF_BE(s)  (80 + (s) * 8)
#define OFF_A(s)   (1024 + (s) * A_BYTES)
#define OFF_B(s)   (1024 + A_STAGES * A_BYTES + (s) * B_BYTES)
#define SMEM_USED  (1024 + A_STAGES * A_BYTES + B_STAGES * B_BYTES)
#define SMEM_TOTAL (SMEM_USED + 1024)

// one compute phase: nkc k-chunks x 9 taps over the pipelined stages
template<bool IS8>
__device__ __forceinline__ void run_phase(
    int nkc, uint32_t sb, int& sa, int& pa, int& sbt, int& pb,
    const uint32_t arb[4], const int ap[4], int ach,
    const int hl[2], const int wc[2], int bch,
    float (*accf)[4][4], int32_t (*acci)[4][4], int lane)
{
    for (int kc = 0; kc < nkc; kc++) {
        MBARRIER_WAIT_PARITY(sb + OFF_BF(sbt), pb);
        const uint32_t bst = sb + OFF_B(sbt);
        #pragma unroll
        for (int tap = 0; tap < 9; tap++) {
            const int dy = tap / 3, dx = tap % 3;
            MBARRIER_WAIT_PARITY(sb + OFF_AF(sa), pa);
            const uint32_t ast = sb + OFF_A(sa);

            uint32_t brb[2]; int bp[2];
            #pragma unroll
            for (int nb2 = 0; nb2 < 2; nb2++) {
                int rsum = hl[nb2] + dy;
                int seg  = rsum >> 1;
                int rloc = (rsum & 1) * PADW + wc[nb2] + dx;
                brb[nb2] = seg * B_SEG + rloc * 128;
                bp[nb2]  = rloc & 7;
            }
            #pragma unroll
            for (int ks = 0; ks < 4; ks++) {
                uint32_t a[4][4], bf[2][4];
                #pragma unroll
                for (int mi = 0; mi < 4; mi++)
                    ldsm4(a[mi], ast + arb[mi] +
                          ((uint32_t)((ks * 2 + ach) ^ ap[mi]) << 4));
                #pragma unroll
                for (int nb2 = 0; nb2 < 2; nb2++)
                    ldsm4(bf[nb2], bst + brb[nb2] +
                          ((uint32_t)((ks * 2 + bch) ^ bp[nb2]) << 4));
                #pragma unroll
                for (int mi = 0; mi < 4; mi++)
                    #pragma unroll
                    for (int ng = 0; ng < 4; ng++) {
                        if (IS8)
                            mma_s8(acci[mi][ng], a[mi], &bf[ng >> 1][(ng & 1) * 2]);
                        else
                            mma16816(accf[mi][ng], a[mi], &bf[ng >> 1][(ng & 1) * 2]);
                    }
            }
            __syncwarp();
            if (lane == 0) MBARRIER_ARRIVE(sb + OFF_AE(sa));
            if (++sa == A_STAGES) { sa = 0; pa ^= 1; }
        }
        __syncwarp();
        if (lane == 0) MBARRIER_ARRIVE(sb + OFF_BE(sbt));
        if (++sbt == B_STAGES) { sbt = 0; pb ^= 1; }
    }
}

__global__ void __launch_bounds__(288, 1) conv_mma_kernel(
    const __grid_constant__ CUtensorMap tm_whi,
    const __grid_constant__ CUtensorMap tm_xhi,
    const __grid_constant__ CUtensorMap tm_wqh,
    const __grid_constant__ CUtensorMap tm_wql,
    const __grid_constant__ CUtensorMap tm_xqh,
    const __grid_constant__ CUtensorMap tm_xql,
    const float* __restrict__ bias, const float* __restrict__ noise,
    const float* __restrict__ nstrength, float* __restrict__ out)
{
    extern __shared__ char smem_raw[];
    uint32_t sb = (smem_to_u32(smem_raw) + 1023u) & ~1023u;

    const int tid  = threadIdx.x;
    const int wid  = tid >> 5;
    const int lane = tid & 31;
    const int p0 = blockIdx.x * 128;
    const int h0 = blockIdx.x * 2;
    const int m0 = blockIdx.y * 128;
    const int b  = blockIdx.z;

    if (tid == 0) {
        #pragma unroll
        for (int s = 0; s < A_STAGES; s++) {
            MBARRIER_INIT(sb + OFF_AF(s), 1);
            MBARRIER_INIT(sb + OFF_AE(s), 8);
        }
        #pragma unroll
        for (int s = 0; s < B_STAGES; s++) {
            MBARRIER_INIT(sb + OFF_BF(s), 1);
            MBARRIER_INIT(sb + OFF_BE(s), 8);
        }
    }
    __syncthreads();

    if (wid == 8) {
        // -------- producer --------
        if (lane == 0) {
            int sa = 0, pa = 1, sbt = 0, pb = 1;
            const int pixstart = h0 * PADW;
            // phase descriptors: {x-map, w-map, nkc, cin-per-chunk}
            #pragma unroll
            for (int ph = 0; ph < 3; ph++) {
                const CUtensorMap* mx = (ph == 0) ? &tm_xqh
                                       : (ph == 1) ? &tm_xql : &tm_xhi;
                const CUtensorMap* mw = (ph == 0) ? &tm_wql
                                       : (ph == 1) ? &tm_wqh : &tm_whi;
                const int nkc  = (ph == 2) ? 8 : 4;
                const int kel  = (ph == 2) ? 64 : 128;  // elements per chunk
                for (int kc = 0; kc < nkc; kc++) {
                    MBARRIER_WAIT_PARITY_RELAXED(sb + OFF_BE(sbt), pb);
                    uint32_t bfb = sb + OFF_BF(sbt);
                    MBARRIER_EXPECT_TX(bfb, B_TX);
                    uint32_t bst = sb + OFF_B(sbt);
                    TMA_LOAD_3D(bst,         mx, kc * kel, pixstart,       b, bfb);
                    TMA_LOAD_3D(bst + B_SEG, mx, kc * kel, pixstart + 132, b, bfb);
                    if (++sbt == B_STAGES) { sbt = 0; pb ^= 1; }
                    for (int tap = 0; tap < 9; tap++) {
                        MBARRIER_WAIT_PARITY_RELAXED(sb + OFF_AE(sa), pa);
                        uint32_t afb = sb + OFF_AF(sa);
                        MBARRIER_EXPECT_TX(afb, A_BYTES);
                        TMA_LOAD_3D(sb + OFF_A(sa), mw, kc * kel, m0, tap, afb);
                        if (++sa == A_STAGES) { sa = 0; pa ^= 1; }
                    }
                }
            }
        }
        return;
    }

    // -------- compute warps 0..7 --------
    const int wm = wid & 1;
    const int wn = wid >> 1;

    const int ach = lane >> 4;
    uint32_t arb[4]; int ap[4];
    #pragma unroll
    for (int mi = 0; mi < 4; mi++) {
        int row = wm * 64 + mi * 16 + (lane & 15);
        arb[mi] = row * 128;
        ap[mi]  = row & 7;
    }
    const int bch = (lane >> 3) & 1;
    int hl[2], wc[2];
    #pragma unroll
    for (int nb2 = 0; nb2 < 2; nb2++) {
        int nl = wn * 32 + nb2 * 16 + (lane & 7) + ((lane >> 4) & 1) * 8;
        hl[nb2] = nl >> 6;
        wc[nb2] = nl & 63;
    }

    float   accf[4][4][4];
    int32_t acci[4][4][4];
    #pragma unroll
    for (int mi = 0; mi < 4; mi++)
        #pragma unroll
        for (int ni = 0; ni < 4; ni++)
            #pragma unroll
            for (int k = 0; k < 4; k++) acci[mi][ni][k] = 0;

    int sa = 0, pa = 0, sbt = 0, pb = 0;

    // phase A: w_lo x x_hi (int8)
    run_phase<true>(4, sb, sa, pa, sbt, pb, arb, ap, ach, hl, wc, bch,
                    accf, acci, lane);
    #pragma unroll
    for (int mi = 0; mi < 4; mi++)
        #pragma unroll
        for (int ni = 0; ni < 4; ni++)
            #pragma unroll
            for (int k = 0; k < 4; k++) {
                accf[mi][ni][k] = CA_SCALE * (float)acci[mi][ni][k];
                acci[mi][ni][k] = 0;
            }
    // phase B: w_hi x x_lo (int8)
    run_phase<true>(4, sb, sa, pa, sbt, pb, arb, ap, ach, hl, wc, bch,
                    accf, acci, lane);
    #pragma unroll
    for (int mi = 0; mi < 4; mi++)
        #pragma unroll
        for (int ni = 0; ni < 4; ni++)
            #pragma unroll
            for (int k = 0; k < 4; k++)
                accf[mi][ni][k] += CB_SCALE * (float)acci[mi][ni][k];
    // phase C: w_hi x x_hi (fp16, main term)
    run_phase<false>(8, sb, sa, pa, sbt, pb, arb, ap, ach, hl, wc, bch,
                     accf, acci, lane);

    // -------- epilogue --------
    const float ns = nstrength[0];
    #pragma unroll
    for (int mi = 0; mi < 4; mi++) {
        const int mrow = m0 + wm * 64 + mi * 16 + (lane >> 2);
        const float dc0 = g_dcoef[b * COUT + mrow];
        const float dc1 = g_dcoef[b * COUT + mrow + 8];
        const float bv0 = bias[mrow];
        const float bv1 = bias[mrow + 8];
        #pragma unroll
        for (int ni = 0; ni < 4; ni++) {
            const int pix = p0 + wn * 32 + ni * 8 + ((lane & 3) << 1);
            const float2 nzv = *reinterpret_cast<const float2*>(noise + pix);
            float v0 = accf[mi][ni][0] * dc0 + nzv.x * ns + bv0;
            float v1 = accf[mi][ni][1] * dc0 + nzv.y * ns + bv0;
            float v2 = accf[mi][ni][2] * dc1 + nzv.x * ns + bv1;
            float v3 = accf[mi][ni][3] * dc1 + nzv.y * ns + bv1;
            v0 = (v0 > 0.f ? v0 : LRELU * v0) * GAINV;
            v1 = (v1 > 0.f ? v1 : LRELU * v1) * GAINV;
            v2 = (v2 > 0.f ? v2 : LRELU * v2) * GAINV;
            v3 = (v3 > 0.f ? v3 : LRELU * v3) * GAINV;
            float2 r0 = {v0, v1}, r1 = {v2, v3};
            *reinterpret_cast<float2*>(
                out + ((size_t)(b * COUT + mrow) * 4096) + pix) = r0;
            *reinterpret_cast<float2*>(
                out + ((size_t)(b * COUT + mrow + 8) * 4096) + pix) = r1;
        }
    }
}

// ---------------------------------------------------------------------------
// Host launch
// ---------------------------------------------------------------------------
typedef CUresult (*PFN_tmapEncode)(
    CUtensorMap*, CUtensorMapDataType, cuuint32_t, void*,
    const cuuint64_t*, const cuuint64_t*, const cuuint32_t*, const cuuint32_t*,
    CUtensorMapInterleave, CUtensorMapSwizzle, CUtensorMapL2promotion,
    CUtensorMapFloatOOBfill);

static void make_map_3d(PFN_tmapEncode enc, CUtensorMap* m, void* base,
                        CUtensorMapDataType dt, size_t esz,
                        cuuint64_t d0, cuuint64_t d1, cuuint64_t d2,
                        cuuint32_t b0, cuuint32_t b1) {
    cuuint64_t dims[3] = {d0, d1, d2};
    cuuint64_t strides[2] = {d0 * esz, d0 * d1 * esz};
    cuuint32_t box[3] = {b0, b1, 1};
    cuuint32_t es[3] = {1, 1, 1};
    enc(m, dt, 3, base, dims, strides, box, es,
        CU_TENSOR_MAP_INTERLEAVE_NONE, CU_TENSOR_MAP_SWIZZLE_128B,
        CU_TENSOR_MAP_L2_PROMOTION_L2_128B, CU_TENSOR_MAP_FLOAT_OOB_FILL_NONE);
}

extern "C" void kernel_launch(void* const* d_in, const int* in_sizes, int n_in,
                              void* d_out, int out_size) {
    const float* x    = (const float*)d_in[0];
    const float* w    = (const float*)d_in[1];
    const float* wt   = (const float*)d_in[2];
    const float* aw   = (const float*)d_in[3];
    const float* ab   = (const float*)d_in[4];
    const float* bias = (const float*)d_in[5];
    const float* nz   = (const float*)d_in[6];
    const float* ns   = (const float*)d_in[7];
    float* out = (float*)d_out;

    styles_kernel<<<(B * CIN * 32 + 255) / 256, 256>>>(w, aw, ab);
    wsq_kernel<<<(COUT * CIN + 255) / 256, 256>>>(wt);
    dcoef_kernel<<<(B * COUT * 32 + 255) / 256, 256>>>();
    wsplit_kernel<<<(COUT * CIN * 9 + 255) / 256, 256>>>(wt);
    xborder_kernel<<<(B * NPIX + 255) / 256, 256>>>();
    xsplit_kernel<<<dim3(RES, B), 256>>>(x);

    void* encp = nullptr;
    cudaDriverEntryPointQueryResult qr;
    cudaGetDriverEntryPointByVersion("cuTensorMapEncodeTiled", &encp, 12000,
                                     cudaEnableDefault, &qr);
    PFN_tmapEncode enc = (PFN_tmapEncode)encp;

    void *p_whi, *p_xhi, *p_wqh, *p_wql, *p_xqh, *p_xql;
    cudaGetSymbolAddress(&p_whi, g_w_hi);
    cudaGetSymbolAddress(&p_xhi, g_xs_hi);
    cudaGetSymbolAddress(&p_wqh, g_wq_hi);
    cudaGetSymbolAddress(&p_wql, g_wq_lo);
    cudaGetSymbolAddress(&p_xqh, g_xq_hi);
    cudaGetSymbolAddress(&p_xql, g_xq_lo);

    CUtensorMap tm_whi, tm_xhi, tm_wqh, tm_wql, tm_xqh, tm_xql;
    make_map_3d(enc, &tm_whi, p_whi, CU_TENSOR_MAP_DATA_TYPE_FLOAT16, 2,
                CIN, COUT, 9, 64, 128);
    make_map_3d(enc, &tm_xhi, p_xhi, CU_TENSOR_MAP_DATA_TYPE_FLOAT16, 2,
                CIN, NPIX, B, 64, 132);
    make_map_3d(enc, &tm_wqh, p_wqh, CU_TENSOR_MAP_DATA_TYPE_UINT8, 1,
                CIN, COUT, 9, 128, 128);
    make_map_3d(enc, &tm_wql, p_wql, CU_TENSOR_MAP_DATA_TYPE_UINT8, 1,
                CIN, COUT, 9, 128, 128);
    make_map_3d(enc, &tm_xqh, p_xqh, CU_TENSOR_MAP_DATA_TYPE_UINT8, 1,
                CIN, NPIX, B, 128, 132);
    make_map_3d(enc, &tm_xql, p_xql, CU_TENSOR_MAP_DATA_TYPE_UINT8, 1,
                CIN, NPIX, B, 128, 132);

    cudaFuncSetAttribute(conv_mma_kernel,
                         cudaFuncAttributeMaxDynamicSharedMemorySize, SMEM_TOTAL);
    dim3 grid(32, 4, B);
    conv_mma_kernel<<<grid, 288, SMEM_TOTAL>>>(
        tm_whi, tm_xhi, tm_wqh, tm_wql, tm_xqh, tm_xql, bias, nz, ns, out);
}

// round 5
// speedup vs baseline: 3.6379x; 3.6379x over previous
#include <cuda_runtime.h>
#include <cuda.h>
#include <cuda_fp16.h>
#include <cstdint>

#define B     16
#define CIN   512
#define COUT  512
#define WDIM  512
#define RES   64
#define LRELU 0.2f
#define GAINV 1.4142135623730951f
#define PADW  66
#define NPIX  (PADW * PADW)   // 4356

// ---------------- scratch (device globals; no allocation allowed) ----------
__device__ float g_styles[B * CIN];
__device__ float g_wsq[COUT * CIN];
__device__ float g_dcoef[B * COUT];
__device__ __align__(1024) __half g_xs_hi[(size_t)B * NPIX * CIN];
__device__ __align__(1024) __half g_w_hi [(size_t)9 * COUT * CIN];
__device__ __align__(1024) __half g_w_lo [(size_t)9 * COUT * CIN];

// ---------------- PTX helpers ----------------------------------------------
__device__ __forceinline__ uint32_t smem_to_u32(const void* p) {
    uint32_t a;
    asm("{ .reg .u64 t; cvta.to.shared.u64 t, %1; cvt.u32.u64 %0, t; }"
        : "=r"(a) : "l"(p));
    return a;
}

#define MBARRIER_INIT(mbar, count) \
    asm volatile("mbarrier.init.shared.b64 [%0], %1;" \
        :: "r"((uint32_t)(mbar)), "r"((uint32_t)(count)) : "memory")
#define MBARRIER_EXPECT_TX(mbar, tx) \
    asm volatile("mbarrier.arrive.expect_tx.shared.b64 _, [%0], %1;" \
        :: "r"((uint32_t)(mbar)), "r"((uint32_t)(tx)) : "memory")
#define MBARRIER_ARRIVE(mbar) \
    asm volatile("mbarrier.arrive.shared.b64 _, [%0];" \
        :: "r"((uint32_t)(mbar)) : "memory")

#define MBARRIER_WAIT_PARITY(mbar, par) do { \
    uint32_t _m = (uint32_t)(mbar); uint32_t _p = (uint32_t)(par); uint32_t _d; \
    asm volatile("{\n\t.reg .pred p;\n\t" \
        "mbarrier.try_wait.parity.acquire.cta.shared::cta.b64 p, [%1], %2;\n\t" \
        "selp.b32 %0, 1, 0, p;\n\t}" : "=r"(_d) : "r"(_m), "r"(_p) : "memory"); \
    if (!_d) { \
        asm volatile("{\n\t.reg .pred P1;\n\tWL_%=:\n\t" \
            "mbarrier.try_wait.parity.acquire.cta.shared::cta.b64 P1, [%0], %1, 0x989680;\n\t" \
            "@P1 bra.uni WD_%=;\n\tbra.uni WL_%=;\n\tWD_%=:\n\t}" \
            :: "r"(_m), "r"(_p) : "memory"); \
    } } while (0)

#define MBARRIER_WAIT_PARITY_RELAXED(mbar, par) do { \
    uint32_t _m = (uint32_t)(mbar); uint32_t _p = (uint32_t)(par); uint32_t _d; \
    asm volatile("{\n\t.reg .pred p;\n\t" \
        "mbarrier.try_wait.parity.relaxed.cta.shared::cta.b64 p, [%1], %2, 0x989680;\n\t" \
        "selp.b32 %0, 1, 0, p;\n\t}" : "=r"(_d) : "r"(_m), "r"(_p) : "memory"); \
    if (!_d) { \
        asm volatile("{\n\t.reg .pred P1;\n\tWL_%=:\n\t" \
            "mbarrier.try_wait.parity.relaxed.cta.shared::cta.b64 P1, [%0], %1, 0x989680;\n\t" \
            "@P1 bra.uni WD_%=;\n\tbra.uni WL_%=;\n\tWD_%=:\n\t}" \
            :: "r"(_m), "r"(_p) : "memory"); \
    } } while (0)

#define TMA_LOAD_3D(smem_addr, tmap, cx, cy, cz, mbar) \
    asm volatile("cp.async.bulk.tensor.3d.shared::cta.global.tile.mbarrier::complete_tx::bytes " \
        "[%0], [%1, {%2, %3, %4}], [%5];" \
        :: "r"((uint32_t)(smem_addr)), "l"(tmap), "r"((int32_t)(cx)), \
           "r"((int32_t)(cy)), "r"((int32_t)(cz)), "r"((uint32_t)(mbar)) : "memory")

__device__ __forceinline__ void ldsm4(uint32_t* r, uint32_t addr) {
    asm volatile("ldmatrix.sync.aligned.m8n8.x4.shared.b16 {%0,%1,%2,%3}, [%4];"
        : "=r"(r[0]), "=r"(r[1]), "=r"(r[2]), "=r"(r[3]) : "r"(addr));
}
__device__ __forceinline__ void mma16816(float* c, const uint32_t* a,
                                         const uint32_t* b) {
    asm volatile("mma.sync.aligned.m16n8k16.row.col.f32.f16.f16.f32 "
        "{%0,%1,%2,%3}, {%4,%5,%6,%7}, {%8,%9}, {%0,%1,%2,%3};"
        : "+f"(c[0]), "+f"(c[1]), "+f"(c[2]), "+f"(c[3])
        : "r"(a[0]), "r"(a[1]), "r"(a[2]), "r"(a[3]), "r"(b[0]), "r"(b[1]));
}

// ---------------------------------------------------------------------------
// Prep kernels
// ---------------------------------------------------------------------------
__global__ void styles_kernel(const float* __restrict__ w,
                              const float* __restrict__ aw,
                              const float* __restrict__ ab) {
    int warp = (blockIdx.x * blockDim.x + threadIdx.x) >> 5;
    int lane = threadIdx.x & 31;
    if (warp >= B * CIN) return;
    int b = warp / CIN, c = warp % CIN;
    const float* wr = w + b * WDIM;
    const float* ar = aw + c * WDIM;
    float sum = 0.f;
    for (int d = lane; d < WDIM; d += 32) sum += wr[d] * ar[d];
    #pragma unroll
    for (int o = 16; o; o >>= 1) sum += __shfl_xor_sync(0xffffffffu, sum, o);
    if (lane == 0) g_styles[warp] = sum * 0.044194173824159216f + ab[c];
}

__global__ void wsq_kernel(const float* __restrict__ weight) {
    int i = blockIdx.x * blockDim.x + threadIdx.x;
    if (i >= COUT * CIN) return;
    const float* p = weight + (size_t)i * 9;
    float s = 0.f;
    #pragma unroll
    for (int k = 0; k < 9; k++) s += p[k] * p[k];
    g_wsq[i] = s;
}

__global__ void dcoef_kernel() {
    int warp = (blockIdx.x * blockDim.x + threadIdx.x) >> 5;
    int lane = threadIdx.x & 31;
    if (warp >= B * COUT) return;
    int b = warp / COUT, o = warp % COUT;
    const float* sr = g_styles + b * CIN;
    const float* wr = g_wsq + o * CIN;
    float sum = 0.f;
    for (int c = lane; c < CIN; c += 32) {
        float s = sr[c];
        sum += s * s * wr[c];
    }
    #pragma unroll
    for (int k = 16; k; k >>= 1) sum += __shfl_xor_sync(0xffffffffu, sum, k);
    if (lane == 0) g_dcoef[warp] = rsqrtf(sum + 1e-8f);
}

// weight [oc][cin][9] fp32 -> w_hi / w_lo fp16 at [tap][oc][cin]
__global__ void wsplit_kernel(const float* __restrict__ wt) {
    int i = blockIdx.x * blockDim.x + threadIdx.x;
    if (i >= COUT * CIN * 9) return;
    int cin = i % CIN;
    int rest = i / CIN;
    int oc = rest % COUT;
    int tap = rest / COUT;
    float v = wt[((size_t)oc * CIN + cin) * 9 + tap];
    __half hv = __float2half_rn(v);
    __half lv = __float2half_rn(v - __half2float(hv));
    size_t o = ((size_t)tap * COUT + oc) * CIN + cin;
    g_w_hi[o] = hv;
    g_w_lo[o] = lv;
}

// x [b][c][64][64] * style -> x_hi fp16 [b][pix][c]; also zeroes pad borders.
// grid (66, B): hh = padded row index.
__global__ __launch_bounds__(256) void xsplit_kernel(const float* __restrict__ x) {
    __shared__ float s[64][65];
    int hh = blockIdx.x, b = blockIdx.y;
    int tid = threadIdx.x;

    if (hh == 0 || hh == PADW - 1) {
        // zero whole padded row: 66 pix * 512 ch * 2B = 4224 uint4
        uint4 z = {0, 0, 0, 0};
        uint4* p = (uint4*)(g_xs_hi + ((size_t)b * NPIX + (size_t)hh * PADW) * CIN);
        for (int i = tid; i < PADW * CIN / 8; i += 256) p[i] = z;
        return;
    }
    // zero the two border pixels of this row (cols 0 and 65)
    {
        uint4 z = {0, 0, 0, 0};
        uint4* p0 = (uint4*)(g_xs_hi + ((size_t)b * NPIX + (size_t)hh * PADW) * CIN);
        uint4* p1 = (uint4*)(g_xs_hi + ((size_t)b * NPIX + (size_t)hh * PADW + 65) * CIN);
        if (tid < 64)       p0[tid] = z;
        else if (tid < 128) p1[tid - 64] = z;
    }
    const int h = hh - 1;
    const int rowbase = hh * PADW + 1;
    for (int c0 = 0; c0 < CIN; c0 += 64) {
        #pragma unroll
        for (int i = tid; i < 4096; i += 256) {
            int cc = i >> 6, w = i & 63;
            s[cc][w] = x[(((size_t)b * CIN + c0 + cc) * RES + h) * RES + w]
                       * g_styles[b * CIN + c0 + cc];
        }
        __syncthreads();
        #pragma unroll
        for (int i = tid; i < 4096; i += 256) {
            int w = i >> 6, cc = i & 63;
            g_xs_hi[((size_t)b * NPIX + rowbase + w) * CIN + c0 + cc]
                = __float2half_rn(s[cc][w]);
        }
        __syncthreads();
    }
}

// ---------------------------------------------------------------------------
// Main HMMA conv kernel (2 fp16 passes: w_hi*x_hi + w_lo*x_hi).
// Grid (32 n-tiles, 4 m-tiles, 16 b). 288 threads = 8 compute warps + 1 TMA.
// CTA tile: M=128 oc x N=128 pixels. Warp tile m64 x n32.
// K loop: 8 cin-chunks(64); per chunk one B tile serves 2 w-sets x 9 taps.
// ---------------------------------------------------------------------------
#define A_STAGES 4
#define B_STAGES 2
#define A_BYTES  16384          // 128 rows x 128B
#define B_SEG    17408          // 136-row slot (132 used), 1024-aligned
#define B_BYTES  (2 * B_SEG)
#define B_TX     33792          // 264 rows x 128B

#define OFF_AF(s)  ((s) * 8)
#define OFF_AE(s)  (32 + (s) * 8)
#define OFF_BF(s)  (64 + (s) * 8)
#define OFF_BE(s)  (80 + (s) * 8)
#define OFF_A(s)   (1024 + (s) * A_BYTES)
#define OFF_B(s)   (1024 + A_STAGES * A_BYTES + (s) * B_BYTES)
#define SMEM_USED  (1024 + A_STAGES * A_BYTES + B_STAGES * B_BYTES)
#define SMEM_TOTAL (SMEM_USED + 1024)

__global__ void __launch_bounds__(288, 1) conv_mma_kernel(
    const __grid_constant__ CUtensorMap tm_whi,
    const __grid_constant__ CUtensorMap tm_wlo,
    const __grid_constant__ CUtensorMap tm_xhi,
    const float* __restrict__ bias, const float* __restrict__ noise,
    const float* __restrict__ nstrength, float* __restrict__ out)
{
    extern __shared__ char smem_raw[];
    uint32_t sb = (smem_to_u32(smem_raw) + 1023u) & ~1023u;

    const int tid  = threadIdx.x;
    const int wid  = tid >> 5;
    const int lane = tid & 31;
    const int p0 = blockIdx.x * 128;
    const int h0 = blockIdx.x * 2;
    const int m0 = blockIdx.y * 128;
    const int b  = blockIdx.z;

    if (tid == 0) {
        #pragma unroll
        for (int s = 0; s < A_STAGES; s++) {
            MBARRIER_INIT(sb + OFF_AF(s), 1);
            MBARRIER_INIT(sb + OFF_AE(s), 8);
        }
        #pragma unroll
        for (int s = 0; s < B_STAGES; s++) {
            MBARRIER_INIT(sb + OFF_BF(s), 1);
            MBARRIER_INIT(sb + OFF_BE(s), 8);
        }
    }
    __syncthreads();

    if (wid == 8) {
        // -------- producer --------
        if (lane == 0) {
            int sa = 0, pa = 1, sbt = 0, pb = 1;
            const int pixstart = h0 * PADW;
            for (int kc = 0; kc < 8; kc++) {
                MBARRIER_WAIT_PARITY_RELAXED(sb + OFF_BE(sbt), pb);
                uint32_t bfb = sb + OFF_BF(sbt);
                MBARRIER_EXPECT_TX(bfb, B_TX);
                uint32_t bst = sb + OFF_B(sbt);
                TMA_LOAD_3D(bst,         &tm_xhi, kc * 64, pixstart,       b, bfb);
                TMA_LOAD_3D(bst + B_SEG, &tm_xhi, kc * 64, pixstart + 132, b, bfb);
                if (++sbt == B_STAGES) { sbt = 0; pb ^= 1; }
                #pragma unroll
                for (int wp = 0; wp < 2; wp++) {
                    const CUtensorMap* mw = wp ? &tm_wlo : &tm_whi;
                    for (int tap = 0; tap < 9; tap++) {
                        MBARRIER_WAIT_PARITY_RELAXED(sb + OFF_AE(sa), pa);
                        uint32_t afb = sb + OFF_AF(sa);
                        MBARRIER_EXPECT_TX(afb, A_BYTES);
                        TMA_LOAD_3D(sb + OFF_A(sa), mw, kc * 64, m0, tap, afb);
                        if (++sa == A_STAGES) { sa = 0; pa ^= 1; }
                    }
                }
            }
        }
        return;
    }

    // -------- compute warps 0..7 --------
    const int wm = wid & 1;
    const int wn = wid >> 1;

    const int ach = lane >> 4;
    uint32_t arb[4]; int ap[4];
    #pragma unroll
    for (int mi = 0; mi < 4; mi++) {
        int row = wm * 64 + mi * 16 + (lane & 15);
        arb[mi] = row * 128;
        ap[mi]  = row & 7;
    }
    const int bch = (lane >> 3) & 1;
    int hl[2], wc[2];
    #pragma unroll
    for (int nb2 = 0; nb2 < 2; nb2++) {
        int nl = wn * 32 + nb2 * 16 + (lane & 7) + ((lane >> 4) & 1) * 8;
        hl[nb2] = nl >> 6;
        wc[nb2] = nl & 63;
    }

    float acc[4][4][4];
    #pragma unroll
    for (int mi = 0; mi < 4; mi++)
        #pragma unroll
        for (int ni = 0; ni < 4; ni++)
            #pragma unroll
            for (int k = 0; k < 4; k++) acc[mi][ni][k] = 0.f;

    int sa = 0, pa = 0, sbt = 0, pb = 0;
    for (int kc = 0; kc < 8; kc++) {
        MBARRIER_WAIT_PARITY(sb + OFF_BF(sbt), pb);
        const uint32_t bst = sb + OFF_B(sbt);
        #pragma unroll
        for (int rep = 0; rep < 2; rep++) {
            #pragma unroll
            for (int tap = 0; tap < 9; tap++) {
                const int dy = tap / 3, dx = tap % 3;
                MBARRIER_WAIT_PARITY(sb + OFF_AF(sa), pa);
                const uint32_t ast = sb + OFF_A(sa);

                uint32_t brb[2]; int bp[2];
                #pragma unroll
                for (int nb2 = 0; nb2 < 2; nb2++) {
                    int rsum = hl[nb2] + dy;
                    int seg  = rsum >> 1;
                    int rloc = (rsum & 1) * PADW + wc[nb2] + dx;
                    brb[nb2] = seg * B_SEG + rloc * 128;
                    bp[nb2]  = rloc & 7;
                }
                #pragma unroll
                for (int ks = 0; ks < 4; ks++) {
                    uint32_t a[4][4], bf[2][4];
                    #pragma unroll
                    for (int mi = 0; mi < 4; mi++)
                        ldsm4(a[mi], ast + arb[mi] +
                              ((uint32_t)((ks * 2 + ach) ^ ap[mi]) << 4));
                    #pragma unroll
                    for (int nb2 = 0; nb2 < 2; nb2++)
                        ldsm4(bf[nb2], bst + brb[nb2] +
                              ((uint32_t)((ks * 2 + bch) ^ bp[nb2]) << 4));
                    #pragma unroll
                    for (int mi = 0; mi < 4; mi++)
                        #pragma unroll
                        for (int ng = 0; ng < 4; ng++)
                            mma16816(acc[mi][ng], a[mi], &bf[ng >> 1][(ng & 1) * 2]);
                }
                __syncwarp();
                if (lane == 0) MBARRIER_ARRIVE(sb + OFF_AE(sa));
                if (++sa == A_STAGES) { sa = 0; pa ^= 1; }
            }
        }
        __syncwarp();
        if (lane == 0) MBARRIER_ARRIVE(sb + OFF_BE(sbt));
        if (++sbt == B_STAGES) { sbt = 0; pb ^= 1; }
    }

    // -------- epilogue --------
    const float ns = nstrength[0];
    #pragma unroll
    for (int mi = 0; mi < 4; mi++) {
        const int mrow = m0 + wm * 64 + mi * 16 + (lane >> 2);
        const float dc0 = g_dcoef[b * COUT + mrow];
        const float dc1 = g_dcoef[b * COUT + mrow + 8];
        const float bv0 = bias[mrow];
        const float bv1 = bias[mrow + 8];
        #pragma unroll
        for (int ni = 0; ni < 4; ni++) {
            const int pix = p0 + wn * 32 + ni * 8 + ((lane & 3) << 1);
            const float2 nzv = *reinterpret_cast<const float2*>(noise + pix);
            float v0 = acc[mi][ni][0] * dc0 + nzv.x * ns + bv0;
            float v1 = acc[mi][ni][1] * dc0 + nzv.y * ns + bv0;
            float v2 = acc[mi][ni][2] * dc1 + nzv.x * ns + bv1;
            float v3 = acc[mi][ni][3] * dc1 + nzv.y * ns + bv1;
            v0 = (v0 > 0.f ? v0 : LRELU * v0) * GAINV;
            v1 = (v1 > 0.f ? v1 : LRELU * v1) * GAINV;
            v2 = (v2 > 0.f ? v2 : LRELU * v2) * GAINV;
            v3 = (v3 > 0.f ? v3 : LRELU * v3) * GAINV;
            float2 r0 = {v0, v1}, r1 = {v2, v3};
            *reinterpret_cast<float2*>(
                out + ((size_t)(b * COUT + mrow) * 4096) + pix) = r0;
            *reinterpret_cast<float2*>(
                out + ((size_t)(b * COUT + mrow + 8) * 4096) + pix) = r1;
        }
    }
}

// ---------------------------------------------------------------------------
// Host launch
// ---------------------------------------------------------------------------
typedef CUresult (*PFN_tmapEncode)(
    CUtensorMap*, CUtensorMapDataType, cuuint32_t, void*,
    const cuuint64_t*, const cuuint64_t*, const cuuint32_t*, const cuuint32_t*,
    CUtensorMapInterleave, CUtensorMapSwizzle, CUtensorMapL2promotion,
    CUtensorMapFloatOOBfill);

static void make_map_3d(PFN_tmapEncode enc, CUtensorMap* m, void* base,
                        cuuint64_t d0, cuuint64_t d1, cuuint64_t d2,
                        cuuint32_t b0, cuuint32_t b1) {
    cuuint64_t dims[3] = {d0, d1, d2};
    cuuint64_t strides[2] = {d0 * 2, d0 * d1 * 2};
    cuuint32_t box[3] = {b0, b1, 1};
    cuuint32_t es[3] = {1, 1, 1};
    enc(m, CU_TENSOR_MAP_DATA_TYPE_FLOAT16, 3, base, dims, strides, box, es,
        CU_TENSOR_MAP_INTERLEAVE_NONE, CU_TENSOR_MAP_SWIZZLE_128B,
        CU_TENSOR_MAP_L2_PROMOTION_L2_128B, CU_TENSOR_MAP_FLOAT_OOB_FILL_NONE);
}

extern "C" void kernel_launch(void* const* d_in, const int* in_sizes, int n_in,
                              void* d_out, int out_size) {
    const float* x    = (const float*)d_in[0];
    const float* w    = (const float*)d_in[1];
    const float* wt   = (const float*)d_in[2];
    const float* aw   = (const float*)d_in[3];
    const float* ab   = (const float*)d_in[4];
    const float* bias = (const float*)d_in[5];
    const float* nz   = (const float*)d_in[6];
    const float* ns   = (const float*)d_in[7];
    float* out = (float*)d_out;

    styles_kernel<<<(B * CIN * 32 + 255) / 256, 256>>>(w, aw, ab);
    wsq_kernel<<<(COUT * CIN + 255) / 256, 256>>>(wt);
    dcoef_kernel<<<(B * COUT * 32 + 255) / 256, 256>>>();
    wsplit_kernel<<<(COUT * CIN * 9 + 255) / 256, 256>>>(wt);
    xsplit_kernel<<<dim3(PADW, B), 256>>>(x);

    void* encp = nullptr;
    cudaDriverEntryPointQueryResult qr;
    cudaGetDriverEntryPointByVersion("cuTensorMapEncodeTiled", &encp, 12000,
                                     cudaEnableDefault, &qr);
    PFN_tmapEncode enc = (PFN_tmapEncode)encp;

    void *p_whi, *p_wlo, *p_xhi;
    cudaGetSymbolAddress(&p_whi, g_w_hi);
    cudaGetSymbolAddress(&p_wlo, g_w_lo);
    cudaGetSymbolAddress(&p_xhi, g_xs_hi);

    CUtensorMap tm_whi, tm_wlo, tm_xhi;
    make_map_3d(enc, &tm_whi, p_whi, CIN, COUT, 9, 64, 128);
    make_map_3d(enc, &tm_wlo, p_wlo, CIN, COUT, 9, 64, 128);
    make_map_3d(enc, &tm_xhi, p_xhi, CIN, NPIX, B, 64, 132);

    cudaFuncSetAttribute(conv_mma_kernel,
                         cudaFuncAttributeMaxDynamicSharedMemorySize, SMEM_TOTAL);
    dim3 grid(32, 4, B);
    conv_mma_kernel<<<grid, 288, SMEM_TOTAL>>>(tm_whi, tm_wlo, tm_xhi,
                                               bias, nz, ns, out);
}

// round 6
// speedup vs baseline: 6.7075x; 1.8438x over previous
#include <cuda_runtime.h>
#include <cuda.h>
#include <cuda_fp16.h>
#include <cstdint>

#define B     16
#define CIN   512
#define COUT  512
#define WDIM  512
#define RES   64
#define LRELU 0.2f
#define GAINV 1.4142135623730951f
#define PADW  66
#define NPIX  (PADW * PADW)   // 4356

// ---------------- scratch (device globals; no allocation allowed) ----------
__device__ float g_styles[B * CIN];
__device__ float g_wsq[COUT * CIN];
__device__ float g_dcoef[B * COUT];
__device__ __align__(1024) __half g_xs_hi[(size_t)B * NPIX * CIN];
__device__ __align__(1024) __half g_w_hi [(size_t)9 * COUT * CIN];

// ---------------- PTX helpers ----------------------------------------------
__device__ __forceinline__ uint32_t smem_to_u32(const void* p) {
    uint32_t a;
    asm("{ .reg .u64 t; cvta.to.shared.u64 t, %1; cvt.u32.u64 %0, t; }"
        : "=r"(a) : "l"(p));
    return a;
}

#define MBARRIER_INIT(mbar, count) \
    asm volatile("mbarrier.init.shared.b64 [%0], %1;" \
        :: "r"((uint32_t)(mbar)), "r"((uint32_t)(count)) : "memory")
#define MBARRIER_EXPECT_TX(mbar, tx) \
    asm volatile("mbarrier.arrive.expect_tx.shared.b64 _, [%0], %1;" \
        :: "r"((uint32_t)(mbar)), "r"((uint32_t)(tx)) : "memory")
#define MBARRIER_ARRIVE(mbar) \
    asm volatile("mbarrier.arrive.shared.b64 _, [%0];" \
        :: "r"((uint32_t)(mbar)) : "memory")

#define MBARRIER_WAIT_PARITY(mbar, par) do { \
    uint32_t _m = (uint32_t)(mbar); uint32_t _p = (uint32_t)(par); uint32_t _d; \
    asm volatile("{\n\t.reg .pred p;\n\t" \
        "mbarrier.try_wait.parity.acquire.cta.shared::cta.b64 p, [%1], %2;\n\t" \
        "selp.b32 %0, 1, 0, p;\n\t}" : "=r"(_d) : "r"(_m), "r"(_p) : "memory"); \
    if (!_d) { \
        asm volatile("{\n\t.reg .pred P1;\n\tWL_%=:\n\t" \
            "mbarrier.try_wait.parity.acquire.cta.shared::cta.b64 P1, [%0], %1, 0x989680;\n\t" \
            "@P1 bra.uni WD_%=;\n\tbra.uni WL_%=;\n\tWD_%=:\n\t}" \
            :: "r"(_m), "r"(_p) : "memory"); \
    } } while (0)

#define MBARRIER_WAIT_PARITY_RELAXED(mbar, par) do { \
    uint32_t _m = (uint32_t)(mbar); uint32_t _p = (uint32_t)(par); uint32_t _d; \
    asm volatile("{\n\t.reg .pred p;\n\t" \
        "mbarrier.try_wait.parity.relaxed.cta.shared::cta.b64 p, [%1], %2, 0x989680;\n\t" \
        "selp.b32 %0, 1, 0, p;\n\t}" : "=r"(_d) : "r"(_m), "r"(_p) : "memory"); \
    if (!_d) { \
        asm volatile("{\n\t.reg .pred P1;\n\tWL_%=:\n\t" \
            "mbarrier.try_wait.parity.relaxed.cta.shared::cta.b64 P1, [%0], %1, 0x989680;\n\t" \
            "@P1 bra.uni WD_%=;\n\tbra.uni WL_%=;\n\tWD_%=:\n\t}" \
            :: "r"(_m), "r"(_p) : "memory"); \
    } } while (0)

#define TMA_LOAD_3D(smem_addr, tmap, cx, cy, cz, mbar) \
    asm volatile("cp.async.bulk.tensor.3d.shared::cta.global.tile.mbarrier::complete_tx::bytes " \
        "[%0], [%1, {%2, %3, %4}], [%5];" \
        :: "r"((uint32_t)(smem_addr)), "l"(tmap), "r"((int32_t)(cx)), \
           "r"((int32_t)(cy)), "r"((int32_t)(cz)), "r"((uint32_t)(mbar)) : "memory")

__device__ __forceinline__ void ldsm4(uint32_t* r, uint32_t addr) {
    asm volatile("ldmatrix.sync.aligned.m8n8.x4.shared.b16 {%0,%1,%2,%3}, [%4];"
        : "=r"(r[0]), "=r"(r[1]), "=r"(r[2]), "=r"(r[3]) : "r"(addr));
}
__device__ __forceinline__ void mma16816(float* c, const uint32_t* a,
                                         const uint32_t* b) {
    asm volatile("mma.sync.aligned.m16n8k16.row.col.f32.f16.f16.f32 "
        "{%0,%1,%2,%3}, {%4,%5,%6,%7}, {%8,%9}, {%0,%1,%2,%3};"
        : "+f"(c[0]), "+f"(c[1]), "+f"(c[2]), "+f"(c[3])
        : "r"(a[0]), "r"(a[1]), "r"(a[2]), "r"(a[3]), "r"(b[0]), "r"(b[1]));
}

// ---------------------------------------------------------------------------
// Prep kernels
// ---------------------------------------------------------------------------
__global__ void styles_kernel(const float* __restrict__ w,
                              const float* __restrict__ aw,
                              const float* __restrict__ ab) {
    int warp = (blockIdx.x * blockDim.x + threadIdx.x) >> 5;
    int lane = threadIdx.x & 31;
    if (warp >= B * CIN) return;
    int b = warp / CIN, c = warp % CIN;
    const float* wr = w + b * WDIM;
    const float* ar = aw + c * WDIM;
    float sum = 0.f;
    for (int d = lane; d < WDIM; d += 32) sum += wr[d] * ar[d];
    #pragma unroll
    for (int o = 16; o; o >>= 1) sum += __shfl_xor_sync(0xffffffffu, sum, o);
    if (lane == 0) g_styles[warp] = sum * 0.044194173824159216f + ab[c];
}

__global__ void wsq_kernel(const float* __restrict__ weight) {
    int i = blockIdx.x * blockDim.x + threadIdx.x;
    if (i >= COUT * CIN) return;
    const float* p = weight + (size_t)i * 9;
    float s = 0.f;
    #pragma unroll
    for (int k = 0; k < 9; k++) s += p[k] * p[k];
    g_wsq[i] = s;
}

__global__ void dcoef_kernel() {
    int warp = (blockIdx.x * blockDim.x + threadIdx.x) >> 5;
    int lane = threadIdx.x & 31;
    if (warp >= B * COUT) return;
    int b = warp / COUT, o = warp % COUT;
    const float* sr = g_styles + b * CIN;
    const float* wr = g_wsq + o * CIN;
    float sum = 0.f;
    for (int c = lane; c < CIN; c += 32) {
        float s = sr[c];
        sum += s * s * wr[c];
    }
    #pragma unroll
    for (int k = 16; k; k >>= 1) sum += __shfl_xor_sync(0xffffffffu, sum, k);
    if (lane == 0) g_dcoef[warp] = rsqrtf(sum + 1e-8f);
}

// weight [oc][cin][9] fp32 -> w_hi fp16 at [tap][oc][cin]
__global__ void wsplit_kernel(const float* __restrict__ wt) {
    int i = blockIdx.x * blockDim.x + threadIdx.x;
    if (i >= COUT * CIN * 9) return;
    int cin = i % CIN;
    int rest = i / CIN;
    int oc = rest % COUT;
    int tap = rest / COUT;
    float v = wt[((size_t)oc * CIN + cin) * 9 + tap];
    g_w_hi[((size_t)tap * COUT + oc) * CIN + cin] = __float2half_rn(v);
}

// x [b][c][64][64] * style -> x_hi fp16 [b][pix][c]; also zeroes pad borders.
// grid (66, B): hh = padded row index.
__global__ __launch_bounds__(256) void xsplit_kernel(const float* __restrict__ x) {
    __shared__ float s[64][65];
    int hh = blockIdx.x, b = blockIdx.y;
    int tid = threadIdx.x;

    if (hh == 0 || hh == PADW - 1) {
        uint4 z = {0, 0, 0, 0};
        uint4* p = (uint4*)(g_xs_hi + ((size_t)b * NPIX + (size_t)hh * PADW) * CIN);
        for (int i = tid; i < PADW * CIN / 8; i += 256) p[i] = z;
        return;
    }
    {
        uint4 z = {0, 0, 0, 0};
        uint4* p0 = (uint4*)(g_xs_hi + ((size_t)b * NPIX + (size_t)hh * PADW) * CIN);
        uint4* p1 = (uint4*)(g_xs_hi + ((size_t)b * NPIX + (size_t)hh * PADW + 65) * CIN);
        if (tid < 64)       p0[tid] = z;
        else if (tid < 128) p1[tid - 64] = z;
    }
    const int h = hh - 1;
    const int rowbase = hh * PADW + 1;
    for (int c0 = 0; c0 < CIN; c0 += 64) {
        #pragma unroll
        for (int i = tid; i < 4096; i += 256) {
            int cc = i >> 6, w = i & 63;
            s[cc][w] = x[(((size_t)b * CIN + c0 + cc) * RES + h) * RES + w]
                       * g_styles[b * CIN + c0 + cc];
        }
        __syncthreads();
        #pragma unroll
        for (int i = tid; i < 4096; i += 256) {
            int w = i >> 6, cc = i & 63;
            g_xs_hi[((size_t)b * NPIX + rowbase + w) * CIN + c0 + cc]
                = __float2half_rn(s[cc][w]);
        }
        __syncthreads();
    }
}

// ---------------------------------------------------------------------------
// Main HMMA conv kernel (single fp16 pass: w_hi * x_hi).
// Grid (32 n-tiles, 4 m-tiles, 16 b). 288 threads = 8 compute warps + 1 TMA.
// CTA tile: M=128 oc x N=128 pixels. Warp tile m64 x n32.
// K loop: 8 cin-chunks(64) x 9 taps; one B tile per chunk serves all 9 taps.
// ---------------------------------------------------------------------------
#define A_STAGES 4
#define B_STAGES 2
#define A_BYTES  16384          // 128 rows x 128B
#define B_SEG    17408          // 136-row slot (132 used), 1024-aligned
#define B_BYTES  (2 * B_SEG)
#define B_TX     33792          // 264 rows x 128B

#define OFF_AF(s)  ((s) * 8)
#define OFF_AE(s)  (32 + (s) * 8)
#define OFF_BF(s)  (64 + (s) * 8)
#define OFF_BE(s)  (80 + (s) * 8)
#define OFF_A(s)   (1024 + (s) * A_BYTES)
#define OFF_B(s)   (1024 + A_STAGES * A_BYTES + (s) * B_BYTES)
#define SMEM_USED  (1024 + A_STAGES * A_BYTES + B_STAGES * B_BYTES)
#define SMEM_TOTAL (SMEM_USED + 1024)

__global__ void __launch_bounds__(288, 1) conv_mma_kernel(
    const __grid_constant__ CUtensorMap tm_whi,
    const __grid_constant__ CUtensorMap tm_xhi,
    const float* __restrict__ bias, const float* __restrict__ noise,
    const float* __restrict__ nstrength, float* __restrict__ out)
{
    extern __shared__ char smem_raw[];
    uint32_t sb = (smem_to_u32(smem_raw) + 1023u) & ~1023u;

    const int tid  = threadIdx.x;
    const int wid  = tid >> 5;
    const int lane = tid & 31;
    const int p0 = blockIdx.x * 128;
    const int h0 = blockIdx.x * 2;
    const int m0 = blockIdx.y * 128;
    const int b  = blockIdx.z;

    if (tid == 0) {
        #pragma unroll
        for (int s = 0; s < A_STAGES; s++) {
            MBARRIER_INIT(sb + OFF_AF(s), 1);
            MBARRIER_INIT(sb + OFF_AE(s), 8);
        }
        #pragma unroll
        for (int s = 0; s < B_STAGES; s++) {
            MBARRIER_INIT(sb + OFF_BF(s), 1);
            MBARRIER_INIT(sb + OFF_BE(s), 8);
        }
    }
    __syncthreads();

    if (wid == 8) {
        // -------- producer --------
        if (lane == 0) {
            int sa = 0, pa = 1, sbt = 0, pb = 1;
            const int pixstart = h0 * PADW;
            for (int kc = 0; kc < 8; kc++) {
                MBARRIER_WAIT_PARITY_RELAXED(sb + OFF_BE(sbt), pb);
                uint32_t bfb = sb + OFF_BF(sbt);
                MBARRIER_EXPECT_TX(bfb, B_TX);
                uint32_t bst = sb + OFF_B(sbt);
                TMA_LOAD_3D(bst,         &tm_xhi, kc * 64, pixstart,       b, bfb);
                TMA_LOAD_3D(bst + B_SEG, &tm_xhi, kc * 64, pixstart + 132, b, bfb);
                if (++sbt == B_STAGES) { sbt = 0; pb ^= 1; }
                for (int tap = 0; tap < 9; tap++) {
                    MBARRIER_WAIT_PARITY_RELAXED(sb + OFF_AE(sa), pa);
                    uint32_t afb = sb + OFF_AF(sa);
                    MBARRIER_EXPECT_TX(afb, A_BYTES);
                    TMA_LOAD_3D(sb + OFF_A(sa), &tm_whi, kc * 64, m0, tap, afb);
                    if (++sa == A_STAGES) { sa = 0; pa ^= 1; }
                }
            }
        }
        return;
    }

    // -------- compute warps 0..7 --------
    const int wm = wid & 1;
    const int wn = wid >> 1;

    const int ach = lane >> 4;
    uint32_t arb[4]; int ap[4];
    #pragma unroll
    for (int mi = 0; mi < 4; mi++) {
        int row = wm * 64 + mi * 16 + (lane & 15);
        arb[mi] = row * 128;
        ap[mi]  = row & 7;
    }
    const int bch = (lane >> 3) & 1;
    int hl[2], wc[2];
    #pragma unroll
    for (int nb2 = 0; nb2 < 2; nb2++) {
        int nl = wn * 32 + nb2 * 16 + (lane & 7) + ((lane >> 4) & 1) * 8;
        hl[nb2] = nl >> 6;
        wc[nb2] = nl & 63;
    }

    float acc[4][4][4];
    #pragma unroll
    for (int mi = 0; mi < 4; mi++)
        #pragma unroll
        for (int ni = 0; ni < 4; ni++)
            #pragma unroll
            for (int k = 0; k < 4; k++) acc[mi][ni][k] = 0.f;

    int sa = 0, pa = 0, sbt = 0, pb = 0;
    for (int kc = 0; kc < 8; kc++) {
        MBARRIER_WAIT_PARITY(sb + OFF_BF(sbt), pb);
        const uint32_t bst = sb + OFF_B(sbt);
        #pragma unroll
        for (int tap = 0; tap < 9; tap++) {
            const int dy = tap / 3, dx = tap % 3;
            MBARRIER_WAIT_PARITY(sb + OFF_AF(sa), pa);
            const uint32_t ast = sb + OFF_A(sa);

            uint32_t brb[2]; int bp[2];
            #pragma unroll
            for (int nb2 = 0; nb2 < 2; nb2++) {
                int rsum = hl[nb2] + dy;
                int seg  = rsum >> 1;
                int rloc = (rsum & 1) * PADW + wc[nb2] + dx;
                brb[nb2] = seg * B_SEG + rloc * 128;
                bp[nb2]  = rloc & 7;
            }
            #pragma unroll
            for (int ks = 0; ks < 4; ks++) {
                uint32_t a[4][4], bf[2][4];
                #pragma unroll
                for (int mi = 0; mi < 4; mi++)
                    ldsm4(a[mi], ast + arb[mi] +
                          ((uint32_t)((ks * 2 + ach) ^ ap[mi]) << 4));
                #pragma unroll
                for (int nb2 = 0; nb2 < 2; nb2++)
                    ldsm4(bf[nb2], bst + brb[nb2] +
                          ((uint32_t)((ks * 2 + bch) ^ bp[nb2]) << 4));
                #pragma unroll
                for (int mi = 0; mi < 4; mi++)
                    #pragma unroll
                    for (int ng = 0; ng < 4; ng++)
                        mma16816(acc[mi][ng], a[mi], &bf[ng >> 1][(ng & 1) * 2]);
            }
            __syncwarp();
            if (lane == 0) MBARRIER_ARRIVE(sb + OFF_AE(sa));
            if (++sa == A_STAGES) { sa = 0; pa ^= 1; }
        }
        __syncwarp();
        if (lane == 0) MBARRIER_ARRIVE(sb + OFF_BE(sbt));
        if (++sbt == B_STAGES) { sbt = 0; pb ^= 1; }
    }

    // -------- epilogue --------
    const float ns = nstrength[0];
    #pragma unroll
    for (int mi = 0; mi < 4; mi++) {
        const int mrow = m0 + wm * 64 + mi * 16 + (lane >> 2);
        const float dc0 = g_dcoef[b * COUT + mrow];
        const float dc1 = g_dcoef[b * COUT + mrow + 8];
        const float bv0 = bias[mrow];
        const float bv1 = bias[mrow + 8];
        #pragma unroll
        for (int ni = 0; ni < 4; ni++) {
            const int pix = p0 + wn * 32 + ni * 8 + ((lane & 3) << 1);
            const float2 nzv = *reinterpret_cast<const float2*>(noise + pix);
            float v0 = acc[mi][ni][0] * dc0 + nzv.x * ns + bv0;
            float v1 = acc[mi][ni][1] * dc0 + nzv.y * ns + bv0;
            float v2 = acc[mi][ni][2] * dc1 + nzv.x * ns + bv1;
            float v3 = acc[mi][ni][3] * dc1 + nzv.y * ns + bv1;
            v0 = (v0 > 0.f ? v0 : LRELU * v0) * GAINV;
            v1 = (v1 > 0.f ? v1 : LRELU * v1) * GAINV;
            v2 = (v2 > 0.f ? v2 : LRELU * v2) * GAINV;
            v3 = (v3 > 0.f ? v3 : LRELU * v3) * GAINV;
            float2 r0 = {v0, v1}, r1 = {v2, v3};
            *reinterpret_cast<float2*>(
                out + ((size_t)(b * COUT + mrow) * 4096) + pix) = r0;
            *reinterpret_cast<float2*>(
                out + ((size_t)(b * COUT + mrow + 8) * 4096) + pix) = r1;
        }
    }
}

// ---------------------------------------------------------------------------
// Host launch
// ---------------------------------------------------------------------------
typedef CUresult (*PFN_tmapEncode)(
    CUtensorMap*, CUtensorMapDataType, cuuint32_t, void*,
    const cuuint64_t*, const cuuint64_t*, const cuuint32_t*, const cuuint32_t*,
    CUtensorMapInterleave, CUtensorMapSwizzle, CUtensorMapL2promotion,
    CUtensorMapFloatOOBfill);

static void make_map_3d(PFN_tmapEncode enc, CUtensorMap* m, void* base,
                        cuuint64_t d0, cuuint64_t d1, cuuint64_t d2,
                        cuuint32_t b0, cuuint32_t b1) {
    cuuint64_t dims[3] = {d0, d1, d2};
    cuuint64_t strides[2] = {d0 * 2, d0 * d1 * 2};
    cuuint32_t box[3] = {b0, b1, 1};
    cuuint32_t es[3] = {1, 1, 1};
    enc(m, CU_TENSOR_MAP_DATA_TYPE_FLOAT16, 3, base, dims, strides, box, es,
        CU_TENSOR_MAP_INTERLEAVE_NONE, CU_TENSOR_MAP_SWIZZLE_128B,
        CU_TENSOR_MAP_L2_PROMOTION_L2_128B, CU_TENSOR_MAP_FLOAT_OOB_FILL_NONE);
}

extern "C" void kernel_launch(void* const* d_in, const int* in_sizes, int n_in,
                              void* d_out, int out_size) {
    const float* x    = (const float*)d_in[0];
    const float* w    = (const float*)d_in[1];
    const float* wt   = (const float*)d_in[2];
    const float* aw   = (const float*)d_in[3];
    const float* ab   = (const float*)d_in[4];
    const float* bias = (const float*)d_in[5];
    const float* nz   = (const float*)d_in[6];
    const float* ns   = (const float*)d_in[7];
    float* out = (float*)d_out;

    styles_kernel<<<(B * CIN * 32 + 255) / 256, 256>>>(w, aw, ab);
    wsq_kernel<<<(COUT * CIN + 255) / 256, 256>>>(wt);
    dcoef_kernel<<<(B * COUT * 32 + 255) / 256, 256>>>();
    wsplit_kernel<<<(COUT * CIN * 9 + 255) / 256, 256>>>(wt);
    xsplit_kernel<<<dim3(PADW, B), 256>>>(x);

    void* encp = nullptr;
    cudaDriverEntryPointQueryResult qr;
    cudaGetDriverEntryPointByVersion("cuTensorMapEncodeTiled", &encp, 12000,
                                     cudaEnableDefault, &qr);
    PFN_tmapEncode enc = (PFN_tmapEncode)encp;

    void *p_whi, *p_xhi;
    cudaGetSymbolAddress(&p_whi, g_w_hi);
    cudaGetSymbolAddress(&p_xhi, g_xs_hi);

    CUtensorMap tm_whi, tm_xhi;
    make_map_3d(enc, &tm_whi, p_whi, CIN, COUT, 9, 64, 128);
    make_map_3d(enc, &tm_xhi, p_xhi, CIN, NPIX, B, 64, 132);

    cudaFuncSetAttribute(conv_mma_kernel,
                         cudaFuncAttributeMaxDynamicSharedMemorySize, SMEM_TOTAL);
    dim3 grid(32, 4, B);
    conv_mma_kernel<<<grid, 288, SMEM_TOTAL>>>(tm_whi, tm_xhi,
                                               bias, nz, ns, out);
}

// round 7
// speedup vs baseline: 7.1767x; 1.0699x over previous
#include <cuda_runtime.h>
#include <cuda.h>
#include <cuda_fp16.h>
#include <cstdint>

#define B     16
#define CIN   512
#define COUT  512
#define WDIM  512
#define RES   64
#define LRELU 0.2f
#define GAINV 1.4142135623730951f
#define TT    16384    // total 2x2 output tiles = B * 32 * 32
#define NC    16       // Winograd coordinates (4x4)

// ---------------- scratch (device globals; no allocation allowed) ----------
__device__ float g_styles[B * CIN];
__device__ float g_wsq[COUT * CIN];
__device__ float g_dcoef[B * COUT];
__device__ __align__(1024) __half g_U[(size_t)NC * COUT * CIN];   // 8.4 MB
__device__ __align__(1024) __half g_V[(size_t)NC * TT * CIN];     // 268 MB
__device__ __align__(1024) float  g_M[(size_t)NC * COUT * TT];    // 536 MB

// ---------------- PTX helpers ----------------------------------------------
__device__ __forceinline__ uint32_t smem_to_u32(const void* p) {
    uint32_t a;
    asm("{ .reg .u64 t; cvta.to.shared.u64 t, %1; cvt.u32.u64 %0, t; }"
        : "=r"(a) : "l"(p));
    return a;
}

#define MBARRIER_INIT(mbar, count) \
    asm volatile("mbarrier.init.shared.b64 [%0], %1;" \
        :: "r"((uint32_t)(mbar)), "r"((uint32_t)(count)) : "memory")
#define MBARRIER_EXPECT_TX(mbar, tx) \
    asm volatile("mbarrier.arrive.expect_tx.shared.b64 _, [%0], %1;" \
        :: "r"((uint32_t)(mbar)), "r"((uint32_t)(tx)) : "memory")
#define MBARRIER_ARRIVE(mbar) \
    asm volatile("mbarrier.arrive.shared.b64 _, [%0];" \
        :: "r"((uint32_t)(mbar)) : "memory")

#define MBARRIER_WAIT_PARITY(mbar, par) do { \
    uint32_t _m = (uint32_t)(mbar); uint32_t _p = (uint32_t)(par); uint32_t _d; \
    asm volatile("{\n\t.reg .pred p;\n\t" \
        "mbarrier.try_wait.parity.acquire.cta.shared::cta.b64 p, [%1], %2;\n\t" \
        "selp.b32 %0, 1, 0, p;\n\t}" : "=r"(_d) : "r"(_m), "r"(_p) : "memory"); \
    if (!_d) { \
        asm volatile("{\n\t.reg .pred P1;\n\tWL_%=:\n\t" \
            "mbarrier.try_wait.parity.acquire.cta.shared::cta.b64 P1, [%0], %1, 0x989680;\n\t" \
            "@P1 bra.uni WD_%=;\n\tbra.uni WL_%=;\n\tWD_%=:\n\t}" \
            :: "r"(_m), "r"(_p) : "memory"); \
    } } while (0)

#define MBARRIER_WAIT_PARITY_RELAXED(mbar, par) do { \
    uint32_t _m = (uint32_t)(mbar); uint32_t _p = (uint32_t)(par); uint32_t _d; \
    asm volatile("{\n\t.reg .pred p;\n\t" \
        "mbarrier.try_wait.parity.relaxed.cta.shared::cta.b64 p, [%1], %2, 0x989680;\n\t" \
        "selp.b32 %0, 1, 0, p;\n\t}" : "=r"(_d) : "r"(_m), "r"(_p) : "memory"); \
    if (!_d) { \
        asm volatile("{\n\t.reg .pred P1;\n\tWL_%=:\n\t" \
            "mbarrier.try_wait.parity.relaxed.cta.shared::cta.b64 P1, [%0], %1, 0x989680;\n\t" \
            "@P1 bra.uni WD_%=;\n\tbra.uni WL_%=;\n\tWD_%=:\n\t}" \
            :: "r"(_m), "r"(_p) : "memory"); \
    } } while (0)

#define TMA_LOAD_3D(smem_addr, tmap, cx, cy, cz, mbar) \
    asm volatile("cp.async.bulk.tensor.3d.shared::cta.global.tile.mbarrier::complete_tx::bytes " \
        "[%0], [%1, {%2, %3, %4}], [%5];" \
        :: "r"((uint32_t)(smem_addr)), "l"(tmap), "r"((int32_t)(cx)), \
           "r"((int32_t)(cy)), "r"((int32_t)(cz)), "r"((uint32_t)(mbar)) : "memory")

__device__ __forceinline__ void ldsm4(uint32_t* r, uint32_t addr) {
    asm volatile("ldmatrix.sync.aligned.m8n8.x4.shared.b16 {%0,%1,%2,%3}, [%4];"
        : "=r"(r[0]), "=r"(r[1]), "=r"(r[2]), "=r"(r[3]) : "r"(addr));
}
__device__ __forceinline__ void mma16816(float* c, const uint32_t* a,
                                         const uint32_t* b) {
    asm volatile("mma.sync.aligned.m16n8k16.row.col.f32.f16.f16.f32 "
        "{%0,%1,%2,%3}, {%4,%5,%6,%7}, {%8,%9}, {%0,%1,%2,%3};"
        : "+f"(c[0]), "+f"(c[1]), "+f"(c[2]), "+f"(c[3])
        : "r"(a[0]), "r"(a[1]), "r"(a[2]), "r"(a[3]), "r"(b[0]), "r"(b[1]));
}

// ---------------------------------------------------------------------------
// Prep kernels
// ---------------------------------------------------------------------------
__global__ void styles_kernel(const float* __restrict__ w,
                              const float* __restrict__ aw,
                              const float* __restrict__ ab) {
    int warp = (blockIdx.x * blockDim.x + threadIdx.x) >> 5;
    int lane = threadIdx.x & 31;
    if (warp >= B * CIN) return;
    int b = warp / CIN, c = warp % CIN;
    const float* wr = w + b * WDIM;
    const float* ar = aw + c * WDIM;
    float sum = 0.f;
    for (int d = lane; d < WDIM; d += 32) sum += wr[d] * ar[d];
    #pragma unroll
    for (int o = 16; o; o >>= 1) sum += __shfl_xor_sync(0xffffffffu, sum, o);
    if (lane == 0) g_styles[warp] = sum * 0.044194173824159216f + ab[c];
}

__global__ void wsq_kernel(const float* __restrict__ weight) {
    int i = blockIdx.x * blockDim.x + threadIdx.x;
    if (i >= COUT * CIN) return;
    const float* p = weight + (size_t)i * 9;
    float s = 0.f;
    #pragma unroll
    for (int k = 0; k < 9; k++) s += p[k] * p[k];
    g_wsq[i] = s;
}

__global__ void dcoef_kernel() {
    int warp = (blockIdx.x * blockDim.x + threadIdx.x) >> 5;
    int lane = threadIdx.x & 31;
    if (warp >= B * COUT) return;
    int b = warp / COUT, o = warp % COUT;
    const float* sr = g_styles + b * CIN;
    const float* wr = g_wsq + o * CIN;
    float sum = 0.f;
    for (int c = lane; c < CIN; c += 32) {
        float s = sr[c];
        sum += s * s * wr[c];
    }
    #pragma unroll
    for (int k = 16; k; k >>= 1) sum += __shfl_xor_sync(0xffffffffu, sum, k);
    if (lane == 0) g_dcoef[warp] = rsqrtf(sum + 1e-8f);
}

// weight [oc][cin][3][3] fp32 -> U[coord][oc][cin] fp16, U = G g G^T
__global__ void wtrans_kernel(const float* __restrict__ wt) {
    int i = blockIdx.x * blockDim.x + threadIdx.x;
    if (i >= COUT * CIN) return;
    int cin = i & (CIN - 1);
    int oc  = i >> 9;
    float g[3][3];
    const float* p = wt + ((size_t)oc * CIN + cin) * 9;
    #pragma unroll
    for (int k = 0; k < 9; k++) g[k / 3][k % 3] = p[k];
    // Gg: 4x3 (rows combined)
    float r[4][3];
    #pragma unroll
    for (int j = 0; j < 3; j++) {
        r[0][j] = g[0][j];
        r[1][j] = 0.5f * (g[0][j] + g[1][j] + g[2][j]);
        r[2][j] = 0.5f * (g[0][j] - g[1][j] + g[2][j]);
        r[3][j] = g[2][j];
    }
    // U = (Gg) G^T : 4x4 (cols combined)
    #pragma unroll
    for (int a = 0; a < 4; a++) {
        float u0 = r[a][0];
        float u1 = 0.5f * (r[a][0] + r[a][1] + r[a][2]);
        float u2 = 0.5f * (r[a][0] - r[a][1] + r[a][2]);
        float u3 = r[a][2];
        g_U[(((size_t)(a * 4 + 0) * COUT + oc) * CIN) + cin] = __float2half_rn(u0);
        g_U[(((size_t)(a * 4 + 1) * COUT + oc) * CIN) + cin] = __float2half_rn(u1);
        g_U[(((size_t)(a * 4 + 2) * COUT + oc) * CIN) + cin] = __float2half_rn(u2);
        g_U[(((size_t)(a * 4 + 3) * COUT + oc) * CIN) + cin] = __float2half_rn(u3);
    }
}

// x [b][c][64][64] * style -> V[coord][tile][cin] fp16, V = B^T d B
// grid (32 tile-rows, B). Block handles one tile-row (32 tiles) for all cin.
__global__ __launch_bounds__(256) void xtrans_kernel(const float* __restrict__ x) {
    __shared__ float sx[32][4][66];   // [cin-chunk][patch row][padded col]
    const int ty = blockIdx.x, b = blockIdx.y;
    const int tid = threadIdx.x;

    for (int c0 = 0; c0 < CIN; c0 += 32) {
        // load 4 input rows (2*ty-1 .. 2*ty+2) x 66 padded cols x 32 channels
        for (int i = tid; i < 32 * 4 * 66; i += 256) {
            int cc  = i / 264;
            int rem = i - cc * 264;
            int r   = rem / 66;
            int j   = rem - r * 66;
            int h   = 2 * ty - 1 + r;
            int px  = j - 1;
            float v = 0.f;
            if ((unsigned)h < (unsigned)RES && (unsigned)px < (unsigned)RES)
                v = x[(((size_t)b * CIN + c0 + cc) * RES + h) * RES + px]
                    * g_styles[b * CIN + c0 + cc];
            sx[cc][r][j] = v;
        }
        __syncthreads();
        // transform: 32 tx * 32 cc items
        for (int i = tid; i < 1024; i += 256) {
            int cc = i & 31;
            int tx = i >> 5;
            float D[4][4];
            #pragma unroll
            for (int r = 0; r < 4; r++)
                #pragma unroll
                for (int j = 0; j < 4; j++)
                    D[r][j] = sx[cc][r][2 * tx + j];
            float TD[4][4];
            #pragma unroll
            for (int j = 0; j < 4; j++) {
                TD[0][j] = D[0][j] - D[2][j];
                TD[1][j] = D[1][j] + D[2][j];
                TD[2][j] = D[2][j] - D[1][j];
                TD[3][j] = D[1][j] - D[3][j];
            }
            float V4[4][4];
            #pragma unroll
            for (int a = 0; a < 4; a++) {
                V4[a][0] = TD[a][0] - TD[a][2];
                V4[a][1] = TD[a][1] + TD[a][2];
                V4[a][2] = TD[a][2] - TD[a][1];
                V4[a][3] = TD[a][1] - TD[a][3];
            }
            size_t gt = (size_t)b * 1024 + ty * 32 + tx;
            #pragma unroll
            for (int a = 0; a < 4; a++)
                #pragma unroll
                for (int bb = 0; bb < 4; bb++)
                    g_V[((size_t)(a * 4 + bb) * TT + gt) * CIN + c0 + cc]
                        = __float2half_rn(V4[a][bb]);
        }
        __syncthreads();
    }
}

// ---------------------------------------------------------------------------
// Winograd coordinate GEMM: M[coord][oc][t] = sum_cin U[coord][oc][cin] *
// V[coord][t][cin].  Grid (128 t-tiles, 4 oc-tiles, 16 coords), 288 threads.
// CTA tile M=128 x N=128, K=512 in 8 chunks of 64.  fp32 output.
// ---------------------------------------------------------------------------
#define NSTG      4
#define STG_BYTES 32768   // A(U) 16K + B(V) 16K
#define OFF_F(s)  ((s) * 16)
#define OFF_E(s)  ((s) * 16 + 8)
#define OFF_ST(s) (1024 + (s) * STG_BYTES)
#define SMEM_TOTAL (1024 + NSTG * STG_BYTES + 1024)

__global__ void __launch_bounds__(288, 1) wino_gemm_kernel(
    const __grid_constant__ CUtensorMap tmU,
    const __grid_constant__ CUtensorMap tmV)
{
    extern __shared__ char smem_raw[];
    uint32_t sb = (smem_to_u32(smem_raw) + 1023u) & ~1023u;

    const int tid  = threadIdx.x;
    const int wid  = tid >> 5;
    const int lane = tid & 31;
    const int t0    = blockIdx.x * 128;
    const int m0    = blockIdx.y * 128;
    const int coord = blockIdx.z;

    if (tid == 0) {
        #pragma unroll
        for (int s = 0; s < NSTG; s++) {
            MBARRIER_INIT(sb + OFF_F(s), 1);
            MBARRIER_INIT(sb + OFF_E(s), 8);
        }
    }
    __syncthreads();

    if (wid == 8) {
        if (lane == 0) {
            int st = 0, ph = 1;
            for (int kc = 0; kc < 8; kc++) {
                MBARRIER_WAIT_PARITY_RELAXED(sb + OFF_E(st), ph);
                uint32_t fb = sb + OFF_F(st);
                MBARRIER_EXPECT_TX(fb, STG_BYTES);
                TMA_LOAD_3D(sb + OFF_ST(st),         &tmU, kc * 64, m0, coord, fb);
                TMA_LOAD_3D(sb + OFF_ST(st) + 16384, &tmV, kc * 64, t0, coord, fb);
                if (++st == NSTG) { st = 0; ph ^= 1; }
            }
        }
        return;
    }

    // compute warps 0..7: warp tile m64 x n32
    const int wm = wid & 1;
    const int wn = wid >> 1;

    const int ach = lane >> 4;
    uint32_t arb[4]; int ap[4];
    #pragma unroll
    for (int mi = 0; mi < 4; mi++) {
        int row = wm * 64 + mi * 16 + (lane & 15);
        arb[mi] = row * 128;
        ap[mi]  = row & 7;
    }
    const int bch = (lane >> 3) & 1;
    uint32_t brb[2]; int bp[2];
    #pragma unroll
    for (int nb2 = 0; nb2 < 2; nb2++) {
        int nl = wn * 32 + nb2 * 16 + (lane & 7) + ((lane >> 4) & 1) * 8;
        brb[nb2] = nl * 128;
        bp[nb2]  = nl & 7;
    }

    float acc[4][4][4];
    #pragma unroll
    for (int mi = 0; mi < 4; mi++)
        #pragma unroll
        for (int ni = 0; ni < 4; ni++)
            #pragma unroll
            for (int k = 0; k < 4; k++) acc[mi][ni][k] = 0.f;

    int st = 0, ph = 0;
    for (int kc = 0; kc < 8; kc++) {
        MBARRIER_WAIT_PARITY(sb + OFF_F(st), ph);
        const uint32_t ast = sb + OFF_ST(st);
        const uint32_t bst = ast + 16384;
        #pragma unroll
        for (int ks = 0; ks < 4; ks++) {
            uint32_t a[4][4], bf[2][4];
            #pragma unroll
            for (int mi = 0; mi < 4; mi++)
                ldsm4(a[mi], ast + arb[mi] +
                      ((uint32_t)((ks * 2 + ach) ^ ap[mi]) << 4));
            #pragma unroll
            for (int nb2 = 0; nb2 < 2; nb2++)
                ldsm4(bf[nb2], bst + brb[nb2] +
                      ((uint32_t)((ks * 2 + bch) ^ bp[nb2]) << 4));
            #pragma unroll
            for (int mi = 0; mi < 4; mi++)
                #pragma unroll
                for (int ng = 0; ng < 4; ng++)
                    mma16816(acc[mi][ng], a[mi], &bf[ng >> 1][(ng & 1) * 2]);
        }
        __syncwarp();
        if (lane == 0) MBARRIER_ARRIVE(sb + OFF_E(st));
        if (++st == NSTG) { st = 0; ph ^= 1; }
    }

    // epilogue: write fp32 M
    #pragma unroll
    for (int mi = 0; mi < 4; mi++) {
        const int mrow = m0 + wm * 64 + mi * 16 + (lane >> 2);
        #pragma unroll
        for (int ni = 0; ni < 4; ni++) {
            const int tcol = t0 + wn * 32 + ni * 8 + ((lane & 3) << 1);
            float2 r0 = {acc[mi][ni][0], acc[mi][ni][1]};
            float2 r1 = {acc[mi][ni][2], acc[mi][ni][3]};
            *reinterpret_cast<float2*>(
                g_M + ((size_t)coord * COUT + mrow) * TT + tcol) = r0;
            *reinterpret_cast<float2*>(
                g_M + ((size_t)coord * COUT + mrow + 8) * TT + tcol) = r1;
        }
    }
}

// ---------------------------------------------------------------------------
// Output transform + fused epilogue: Y = A^T M A; demod+noise+bias+lrelu+gain
// grid (TT/256, COUT), 256 threads; thread = one (oc, tile).
// ---------------------------------------------------------------------------
__global__ __launch_bounds__(256) void ytrans_kernel(
    const float* __restrict__ bias, const float* __restrict__ noise,
    const float* __restrict__ nstrength, float* __restrict__ out)
{
    const int t  = blockIdx.x * 256 + threadIdx.x;
    const int oc = blockIdx.y;
    const int b    = t >> 10;
    const int trow = (t >> 5) & 31;
    const int tcol = t & 31;

    float m[16];
    #pragma unroll
    for (int c = 0; c < 16; c++)
        m[c] = g_M[((size_t)c * COUT + oc) * TT + t];

    float TM[2][4];
    #pragma unroll
    for (int bb = 0; bb < 4; bb++) {
        TM[0][bb] = m[0 + bb] + m[4 + bb] + m[8 + bb];
        TM[1][bb] = m[4 + bb] - m[8 + bb] - m[12 + bb];
    }
    float Y[2][2];
    #pragma unroll
    for (int u = 0; u < 2; u++) {
        Y[u][0] = TM[u][0] + TM[u][1] + TM[u][2];
        Y[u][1] = TM[u][1] - TM[u][2] - TM[u][3];
    }

    const float dc  = g_dcoef[b * COUT + oc];
    const float bv  = bias[oc];
    const float nsv = nstrength[0];
    #pragma unroll
    for (int u = 0; u < 2; u++) {
        const int py = 2 * trow + u;
        const int px = 2 * tcol;
        const float2 nz = *reinterpret_cast<const float2*>(noise + py * RES + px);
        float v0 = Y[u][0] * dc + nz.x * nsv + bv;
        float v1 = Y[u][1] * dc + nz.y * nsv + bv;
        v0 = (v0 > 0.f ? v0 : LRELU * v0) * GAINV;
        v1 = (v1 > 0.f ? v1 : LRELU * v1) * GAINV;
        float2 r = {v0, v1};
        *reinterpret_cast<float2*>(
            out + (((size_t)b * COUT + oc) * RES + py) * RES + px) = r;
    }
}

// ---------------------------------------------------------------------------
// Host launch
// ---------------------------------------------------------------------------
typedef CUresult (*PFN_tmapEncode)(
    CUtensorMap*, CUtensorMapDataType, cuuint32_t, void*,
    const cuuint64_t*, const cuuint64_t*, const cuuint32_t*, const cuuint32_t*,
    CUtensorMapInterleave, CUtensorMapSwizzle, CUtensorMapL2promotion,
    CUtensorMapFloatOOBfill);

static void make_map_3d(PFN_tmapEncode enc, CUtensorMap* m, void* base,
                        cuuint64_t d0, cuuint64_t d1, cuuint64_t d2,
                        cuuint32_t b0, cuuint32_t b1) {
    cuuint64_t dims[3] = {d0, d1, d2};
    cuuint64_t strides[2] = {d0 * 2, d0 * d1 * 2};
    cuuint32_t box[3] = {b0, b1, 1};
    cuuint32_t es[3] = {1, 1, 1};
    enc(m, CU_TENSOR_MAP_DATA_TYPE_FLOAT16, 3, base, dims, strides, box, es,
        CU_TENSOR_MAP_INTERLEAVE_NONE, CU_TENSOR_MAP_SWIZZLE_128B,
        CU_TENSOR_MAP_L2_PROMOTION_L2_128B, CU_TENSOR_MAP_FLOAT_OOB_FILL_NONE);
}

extern "C" void kernel_launch(void* const* d_in, const int* in_sizes, int n_in,
                              void* d_out, int out_size) {
    const float* x    = (const float*)d_in[0];
    const float* w    = (const float*)d_in[1];
    const float* wt   = (const float*)d_in[2];
    const float* aw   = (const float*)d_in[3];
    const float* ab   = (const float*)d_in[4];
    const float* bias = (const float*)d_in[5];
    const float* nz   = (const float*)d_in[6];
    const float* ns   = (const float*)d_in[7];
    float* out = (float*)d_out;

    styles_kernel<<<(B * CIN * 32 + 255) / 256, 256>>>(w, aw, ab);
    wsq_kernel<<<(COUT * CIN + 255) / 256, 256>>>(wt);
    dcoef_kernel<<<(B * COUT * 32 + 255) / 256, 256>>>();
    wtrans_kernel<<<(COUT * CIN + 255) / 256, 256>>>(wt);
    xtrans_kernel<<<dim3(32, B), 256>>>(x);

    void* encp = nullptr;
    cudaDriverEntryPointQueryResult qr;
    cudaGetDriverEntryPointByVersion("cuTensorMapEncodeTiled", &encp, 12000,
                                     cudaEnableDefault, &qr);
    PFN_tmapEncode enc = (PFN_tmapEncode)encp;

    void *pU, *pV;
    cudaGetSymbolAddress(&pU, g_U);
    cudaGetSymbolAddress(&pV, g_V);

    CUtensorMap tmU, tmV;
    make_map_3d(enc, &tmU, pU, CIN, COUT, NC, 64, 128);
    make_map_3d(enc, &tmV, pV, CIN, TT, NC, 64, 128);

    cudaFuncSetAttribute(wino_gemm_kernel,
                         cudaFuncAttributeMaxDynamicSharedMemorySize, SMEM_TOTAL);
    dim3 grid(TT / 128, COUT / 128, NC);
    wino_gemm_kernel<<<grid, 288, SMEM_TOTAL>>>(tmU, tmV);

    ytrans_kernel<<<dim3(TT / 256, COUT), 256>>>(bias, nz, ns, out);
}